// round 16
// baseline (speedup 1.0000x reference)
#include <cuda_runtime.h>
#include <cuda_bf16.h>
#include <math.h>
#include <stdint.h>

#define NN 50000
#define NE 800000
#define DIN 64
#define DH  128

// ---------------- device scratch (static, no allocation) ----------------
__device__ float g_bufA[NN * DIN];
__device__ float g_bufB[NN * DIN];
__device__ float g_agg[NN * DIN];
__device__ float g_h1[NN * DH];
__device__ int   g_src[NE];
__device__ int   g_dst[NE];
__device__ int   g_deg[NN];     // zero-initialized; re-zeroed by k_scan_add each call
__device__ int   g_off[NN + 1];
__device__ int   g_cur[NN];
__device__ int   g_csr[NE];
__device__ int   g_bsum[64];
__device__ float g_bn[2 * DH];
// baked weights in mma-fragment order: uint4 = {b0hi, b1hi, b0lo, b1lo}
__device__ uint4 g_w1f[4][4][16][32];
__device__ uint4 g_w2f[4][8][8][32];

// ================= mma helpers (sm_80+ PTX, compiles for compute_103) =================
__device__ __forceinline__ uint32_t smem_u32(const void* p) {
    uint32_t a;
    asm("{ .reg .u64 t; cvta.to.shared.u64 t, %1; cvt.u32.u64 %0, t; }" : "=r"(a) : "l"(p));
    return a;
}
__device__ __forceinline__ void ldmat4(uint32_t* r, uint32_t addr) {
    asm volatile("ldmatrix.sync.aligned.m8n8.x4.shared.b16 {%0,%1,%2,%3}, [%4];"
                 : "=r"(r[0]), "=r"(r[1]), "=r"(r[2]), "=r"(r[3]) : "r"(addr));
}
__device__ __forceinline__ void mma_bf16(float* d, const uint32_t* a, uint32_t b0, uint32_t b1) {
    asm volatile("mma.sync.aligned.m16n8k16.row.col.f32.bf16.bf16.f32 "
                 "{%0,%1,%2,%3}, {%4,%5,%6,%7}, {%8,%9}, {%0,%1,%2,%3};"
                 : "+f"(d[0]), "+f"(d[1]), "+f"(d[2]), "+f"(d[3])
                 : "r"(a[0]), "r"(a[1]), "r"(a[2]), "r"(a[3]), "r"(b0), "r"(b1));
}
__device__ __forceinline__ uint32_t pack_hi2(float x, float y, uint32_t& lo) {
    __nv_bfloat16 hx = __float2bfloat16(x), hy = __float2bfloat16(y);
    __nv_bfloat16 lx = __float2bfloat16(x - __bfloat162float(hx));
    __nv_bfloat16 ly = __float2bfloat16(y - __bfloat162float(hy));
    lo = ((uint32_t)__bfloat16_as_ushort(ly) << 16) | __bfloat16_as_ushort(lx);
    return ((uint32_t)__bfloat16_as_ushort(hy) << 16) | __bfloat16_as_ushort(hx);
}

// ---------------- convert + hist fused: 4 edges per thread (MLP=4) ----------------
#define CONV_THREADS ((NE + 3) / 4)                     // 200000
#define CONV_BLOCKS  ((CONV_THREADS + 255) / 256)       // 782
#define CONV_STRIDE  (CONV_BLOCKS * 256)                // 200192
__global__ __launch_bounds__(256) void k_convert(const void* __restrict__ ei) {
    __shared__ int s_is32;
    int tid = threadIdx.x;
    if (tid < 32) {
        const long long* p = (const long long*)ei;
        int bad = 0;
        #pragma unroll
        for (int u = 0; u < 8; u++) {
            long long v = p[tid * 8 + u];
            bad |= (v < 0 || v >= NN) ? 1 : 0;
        }
        unsigned m = __ballot_sync(0xffffffffu, bad);
        if (tid == 0) s_is32 = (m != 0u);
    }
    __syncthreads();
    int is32 = s_is32;
    int base = blockIdx.x * 256 + tid;
    #pragma unroll
    for (int it = 0; it < 4; it++) {
        int e = base + it * CONV_STRIDE;
        if (e < NE) {
            int s, d;
            if (is32) {
                const int* p = (const int*)ei;
                s = p[e]; d = p[NE + e];
            } else {
                const long long* p = (const long long*)ei;
                s = (int)p[e]; d = (int)p[NE + e];
            }
            s = min(max(s, 0), NN - 1);
            d = min(max(d, 0), NN - 1);
            g_src[e] = s;
            g_dst[e] = d;
            atomicAdd(&g_deg[d], 1);
        }
    }
}

// ---------------- CSR build ----------------
#define SCAN_BLOCKS ((NN + 1023) / 1024)   // 49
// warp-shuffle scan: 2 block barriers instead of 20
__global__ __launch_bounds__(1024) void k_scan_local() {
    __shared__ int warp_sums[32];
    int tid = threadIdx.x, lane = tid & 31, wid = tid >> 5;
    int gid = blockIdx.x * 1024 + tid;
    int v = (gid < NN) ? g_deg[gid] : 0;
    int s = v;
    #pragma unroll
    for (int o = 1; o < 32; o <<= 1) {
        int t = __shfl_up_sync(0xffffffffu, s, o);
        if (lane >= o) s += t;
    }
    if (lane == 31) warp_sums[wid] = s;
    __syncthreads();
    if (wid == 0) {
        int ws = warp_sums[lane];
        #pragma unroll
        for (int o = 1; o < 32; o <<= 1) {
            int t = __shfl_up_sync(0xffffffffu, ws, o);
            if (lane >= o) ws += t;
        }
        warp_sums[lane] = ws;
    }
    __syncthreads();
    int incl = s + (wid ? warp_sums[wid - 1] : 0);
    if (gid < NN) g_off[gid] = incl - v;     // exclusive partial
    if (tid == 1023) g_bsum[blockIdx.x] = incl;
}
// scan_add: every block redundantly computes the 49-entry top-level inclusive
// prefix in smem (cheap), then applies it; also re-zeroes g_deg for next call.
__global__ __launch_bounds__(256) void k_scan_add() {
    __shared__ int sb[64];
    int tid = threadIdx.x;
    if (tid < 64) sb[tid] = (tid < SCAN_BLOCKS) ? g_bsum[tid] : 0;
    __syncthreads();
    for (int o = 1; o < 64; o <<= 1) {
        int t = (tid >= o && tid < 64) ? sb[tid - o] : 0;
        __syncthreads();
        if (tid < 64) sb[tid] += t;           // inclusive
        __syncthreads();
    }
    int i = blockIdx.x * 256 + tid;
    if (i < NN) {
        int blk = i >> 10;
        int add = blk ? sb[blk - 1] : 0;
        int o = g_off[i] + add;
        g_off[i] = o;
        g_cur[i] = o;
        g_deg[i] = 0;                         // ready for next call's convert+hist
    }
    if (i == 0) g_off[NN] = NE;
}
// scatter: 4 edges per thread (MLP=4)
__global__ __launch_bounds__(256) void k_scatter() {
    int base = blockIdx.x * 256 + threadIdx.x;
    #pragma unroll
    for (int it = 0; it < 4; it++) {
        int e = base + it * CONV_STRIDE;
        if (e < NE) {
            int d = g_dst[e];
            int p = atomicAdd(&g_cur[d], 1);
            g_csr[p] = g_src[e];
        }
    }
}

// ---------------- weight bake: fp32 -> bf16 hi/lo fragment-order uint4 ----------------
__global__ void k_prepw(const float* __restrict__ W1, const float* __restrict__ W2) {
    int i = blockIdx.x * blockDim.x + threadIdx.x;
    if (i < 8192) {
        int lane = i & 31, n8 = (i >> 5) & 15, kstep = (i >> 9) & 3, l = i >> 11;
        int n = n8 * 8 + (lane >> 2);
        int k0 = kstep * 16 + 2 * (lane & 3);
        const float* W = W1 + (size_t)l * 8192;       // [k=64][n=128]
        float f00 = W[(k0 + 0) * 128 + n], f01 = W[(k0 + 1) * 128 + n];
        float f10 = W[(k0 + 8) * 128 + n], f11 = W[(k0 + 9) * 128 + n];
        uint4 w;
        w.x = pack_hi2(f00, f01, w.z);
        w.y = pack_hi2(f10, f11, w.w);
        g_w1f[l][kstep][n8][lane] = w;
    } else if (i < 16384) {
        int j = i - 8192;
        int lane = j & 31, n8 = (j >> 5) & 7, kstep = (j >> 8) & 7, l = j >> 11;
        int n = n8 * 8 + (lane >> 2);
        int k0 = kstep * 16 + 2 * (lane & 3);
        const float* W = W2 + (size_t)l * 8192;       // [k=128][n=64]
        float f00 = W[(k0 + 0) * 64 + n], f01 = W[(k0 + 1) * 64 + n];
        float f10 = W[(k0 + 8) * 64 + n], f11 = W[(k0 + 9) * 64 + n];
        uint4 w;
        w.x = pack_hi2(f00, f01, w.z);
        w.y = pack_hi2(f10, f11, w.w);
        g_w2f[l][kstep][n8][lane] = w;
    }
}

// ---------------- softmax aggregation: warp per node, manual 4-wide unroll ----------------
// shift-free + eps-hoisted (R9); manual 4-wide unroll (R14, MLP=4); xc load hoisted.
// Block 0 zeroes g_bn for this layer's bnstat accumulation.
__global__ __launch_bounds__(256) void k_agg(const float* __restrict__ xin, int src_sel) {
    if (blockIdx.x == 0 && threadIdx.x < 2 * DH) g_bn[threadIdx.x] = 0.f;
    const float* x = (src_sel == 0) ? xin : (src_sel == 1) ? g_bufA : g_bufB;
    int w = (blockIdx.x * blockDim.x + threadIdx.x) >> 5;
    if (w >= NN) return;
    int lane = threadIdx.x & 31;
    int beg = g_off[w], end = g_off[w + 1];
    int c = lane * 2;

    float2 xc = *(const float2*)(x + (size_t)w * DIN + c);   // hoisted: independent of loop
    float d0 = 0.f, d1 = 0.f, n0 = 0.f, n1 = 0.f;
    int j = beg;
    #pragma unroll 1
    for (; j + 4 <= end; j += 4) {
        int s0 = g_csr[j], s1 = g_csr[j + 1], s2 = g_csr[j + 2], s3 = g_csr[j + 3];
        float2 va = *(const float2*)(x + (size_t)s0 * DIN + c);
        float2 vb = *(const float2*)(x + (size_t)s1 * DIN + c);
        float2 vc = *(const float2*)(x + (size_t)s2 * DIN + c);
        float2 vd = *(const float2*)(x + (size_t)s3 * DIN + c);
        float ma0 = fmaxf(va.x, 0.f), ma1 = fmaxf(va.y, 0.f);
        float mb0 = fmaxf(vb.x, 0.f), mb1 = fmaxf(vb.y, 0.f);
        float mc0 = fmaxf(vc.x, 0.f), mc1 = fmaxf(vc.y, 0.f);
        float md0 = fmaxf(vd.x, 0.f), md1 = fmaxf(vd.y, 0.f);
        float ea0 = __expf(ma0), ea1 = __expf(ma1);
        float eb0 = __expf(mb0), eb1 = __expf(mb1);
        float ec0 = __expf(mc0), ec1 = __expf(mc1);
        float ed0 = __expf(md0), ed1 = __expf(md1);
        d0 += ea0; n0 = fmaf(ma0, ea0, n0);
        d1 += ea1; n1 = fmaf(ma1, ea1, n1);
        d0 += eb0; n0 = fmaf(mb0, eb0, n0);
        d1 += eb1; n1 = fmaf(mb1, eb1, n1);
        d0 += ec0; n0 = fmaf(mc0, ec0, n0);
        d1 += ec1; n1 = fmaf(mc1, ec1, n1);
        d0 += ed0; n0 = fmaf(md0, ed0, n0);
        d1 += ed1; n1 = fmaf(md1, ed1, n1);
    }
    #pragma unroll 1
    for (; j < end; j++) {
        int s = g_csr[j];
        float2 v = *(const float2*)(x + (size_t)s * DIN + c);
        float m0 = fmaxf(v.x, 0.f);
        float m1 = fmaxf(v.y, 0.f);
        float e0 = __expf(m0);
        float e1 = __expf(m1);
        d0 += e0;  n0 = fmaf(m0, e0, n0);
        d1 += e1;  n1 = fmaf(m1, e1, n1);
    }
    float epsb = (beg < end) ? 1e-7f : 0.f;
    float2 o;
    o.x = n0 / (d0 + 1e-16f) + epsb + xc.x;
    o.y = n1 / (d1 + 1e-16f) + epsb + xc.y;
    *(float2*)(g_agg + (size_t)w * DIN + c) = o;
}

// ---------------- BN stats (separate, cheap L2-read kernel — do NOT fuse into GEMM1) ----------------
__global__ __launch_bounds__(256) void k_bnstat() {
    __shared__ float ss[256], sq[256];
    int col = threadIdx.x & 127;
    int half = threadIdx.x >> 7;
    float s = 0.f, q = 0.f;
    for (int r = blockIdx.x * 2 + half; r < NN; r += gridDim.x * 2) {
        float v = g_h1[(size_t)r * DH + col];
        s += v; q += v * v;
    }
    ss[threadIdx.x] = s; sq[threadIdx.x] = q;
    __syncthreads();
    if (half == 0) {
        atomicAdd(&g_bn[col], ss[col] + ss[col + 128]);
        atomicAdd(&g_bn[DH + col], sq[col] + sq[col + 128]);
    }
}

// ---------------- GEMM1 (mma.sync bf16 split): h1 = agg @ W1 + b1  [128/blk x 128 x K64] ----------------
#define LDA1 72
__global__ __launch_bounds__(256) void k_gemm1_mma(const float* __restrict__ b1, int layer) {
    __shared__ __nv_bfloat16 Ahi[128 * LDA1];
    __shared__ __nv_bfloat16 Alo[128 * LDA1];
    int tid = threadIdx.x, lane = tid & 31, wid = tid >> 5;
    int row0 = blockIdx.x * 128;

    // convert A tile: 128 x 64 fp32 -> hi/lo bf16
    #pragma unroll
    for (int it = 0; it < 16; it++) {
        int f = tid + it * 256;
        int r = f >> 5, c2 = f & 31;
        int row = row0 + r;
        float2 v = make_float2(0.f, 0.f);
        if (row < NN) v = *(const float2*)(g_agg + (size_t)row * DIN + c2 * 2);
        uint32_t lp, hp = pack_hi2(v.x, v.y, lp);
        *(uint32_t*)&Ahi[r * LDA1 + c2 * 2] = hp;
        *(uint32_t*)&Alo[r * LDA1 + c2 * 2] = lp;
    }
    __syncthreads();

    int wm = wid & 3, wn = wid >> 2;      // warp tile: 32 rows x 64 cols
    int mBase = wm * 32, nBase = wn * 64;
    uint32_t a_hi = smem_u32(Ahi), a_lo = smem_u32(Alo);

    float acc[2][8][4];
    #pragma unroll
    for (int tm = 0; tm < 2; tm++)
        #pragma unroll
        for (int tn = 0; tn < 8; tn++)
            #pragma unroll
            for (int q = 0; q < 4; q++) acc[tm][tn][q] = 0.f;

    int lrow = lane & 15;
    int lkof = (lane >> 4) << 3;
    #pragma unroll
    for (int ks = 0; ks < 4; ks++) {
        uint32_t ah[2][4], al[2][4];
        #pragma unroll
        for (int tm = 0; tm < 2; tm++) {
            uint32_t off = ((mBase + tm * 16 + lrow) * LDA1 + ks * 16 + lkof) * 2;
            ldmat4(ah[tm], a_hi + off);
            ldmat4(al[tm], a_lo + off);
        }
        uint4 w[8];
        #pragma unroll
        for (int tn = 0; tn < 8; tn++)
            w[tn] = g_w1f[layer][ks][wn * 8 + tn][lane];
        #pragma unroll
        for (int tm = 0; tm < 2; tm++)
            #pragma unroll
            for (int tn = 0; tn < 8; tn++) {
                mma_bf16(acc[tm][tn], ah[tm], w[tn].x, w[tn].y);
                mma_bf16(acc[tm][tn], ah[tm], w[tn].z, w[tn].w);
                mma_bf16(acc[tm][tn], al[tm], w[tn].x, w[tn].y);
            }
    }

    // epilogue: + bias, store h1 (nothing else — epilogue is register-saturated)
    int qrow = lane >> 2, qcol = (lane & 3) * 2;
    #pragma unroll
    for (int tm = 0; tm < 2; tm++) {
        int r0 = row0 + mBase + tm * 16 + qrow;
        #pragma unroll
        for (int tn = 0; tn < 8; tn++) {
            int c = nBase + tn * 8 + qcol;
            float bx = b1[c], by = b1[c + 1];
            if (r0 < NN)
                *(float2*)(g_h1 + (size_t)r0 * DH + c) = make_float2(acc[tm][tn][0] + bx, acc[tm][tn][1] + by);
            if (r0 + 8 < NN)
                *(float2*)(g_h1 + (size_t)(r0 + 8) * DH + c) = make_float2(acc[tm][tn][2] + bx, acc[tm][tn][3] + by);
        }
    }
}

// ---------------- mish ----------------
__device__ __forceinline__ float mishf(float v) {
    float e  = __expf(v);
    float sp = (v > 15.f) ? v : log1pf(e);
    return v * tanhf(sp);
}

// ---------------- GEMM2 (mma.sync bf16 split) + inline BN finalize ----------------
#define LDA2 136
__global__ __launch_bounds__(256) void k_gemm2_mma(const float* __restrict__ b2,
                                                   const float* __restrict__ gamma,
                                                   const float* __restrict__ beta,
                                                   float* __restrict__ outp,
                                                   int layer, int dst_sel, int do_mish) {
    __shared__ __nv_bfloat16 Ahi[128 * LDA2];
    __shared__ __nv_bfloat16 Alo[128 * LDA2];
    __shared__ float ssc[DH], ssh[DH];
    int tid = threadIdx.x, lane = tid & 31, wid = tid >> 5;
    float* out = (dst_sel == 0) ? g_bufA : (dst_sel == 1) ? g_bufB : outp;

    if (tid < DH) {
        float mu  = g_bn[tid] * (1.0f / NN);
        float var = g_bn[DH + tid] * (1.0f / NN) - mu * mu;
        float rs  = rsqrtf(var + 1e-5f);
        float sc  = rs * gamma[tid];
        ssc[tid] = sc;
        ssh[tid] = beta[tid] - mu * sc;
    }
    __syncthreads();

    int row0 = blockIdx.x * 128;
    #pragma unroll
    for (int it = 0; it < 32; it++) {
        int f = tid + it * 256;
        int r = f >> 6, c2 = f & 63;
        int row = row0 + r;
        float2 v = make_float2(0.f, 0.f);
        if (row < NN) v = *(const float2*)(g_h1 + (size_t)row * DH + c2 * 2);
        int c = c2 * 2;
        float a0 = fmaxf(fmaf(v.x, ssc[c], ssh[c]), 0.f);
        float a1 = fmaxf(fmaf(v.y, ssc[c + 1], ssh[c + 1]), 0.f);
        uint32_t lp, hp = pack_hi2(a0, a1, lp);
        *(uint32_t*)&Ahi[r * LDA2 + c] = hp;
        *(uint32_t*)&Alo[r * LDA2 + c] = lp;
    }
    __syncthreads();

    int wm = wid & 3, wn = wid >> 2;      // warp tile: 32 rows x 32 cols
    int mBase = wm * 32, nBase = wn * 32;
    uint32_t a_hi = smem_u32(Ahi), a_lo = smem_u32(Alo);

    float acc[2][4][4];
    #pragma unroll
    for (int tm = 0; tm < 2; tm++)
        #pragma unroll
        for (int tn = 0; tn < 4; tn++)
            #pragma unroll
            for (int q = 0; q < 4; q++) acc[tm][tn][q] = 0.f;

    int lrow = lane & 15;
    int lkof = (lane >> 4) << 3;
    #pragma unroll
    for (int ks = 0; ks < 8; ks++) {
        uint32_t ah[2][4], al[2][4];
        #pragma unroll
        for (int tm = 0; tm < 2; tm++) {
            uint32_t off = ((mBase + tm * 16 + lrow) * LDA2 + ks * 16 + lkof) * 2;
            ldmat4(ah[tm], a_hi + off);
            ldmat4(al[tm], a_lo + off);
        }
        uint4 w[4];
        #pragma unroll
        for (int tn = 0; tn < 4; tn++)
            w[tn] = g_w2f[layer][ks][wn * 4 + tn][lane];
        #pragma unroll
        for (int tm = 0; tm < 2; tm++)
            #pragma unroll
            for (int tn = 0; tn < 4; tn++) {
                mma_bf16(acc[tm][tn], ah[tm], w[tn].x, w[tn].y);
                mma_bf16(acc[tm][tn], ah[tm], w[tn].z, w[tn].w);
                mma_bf16(acc[tm][tn], al[tm], w[tn].x, w[tn].y);
            }
    }

    int qrow = lane >> 2, qcol = (lane & 3) * 2;
    #pragma unroll
    for (int tm = 0; tm < 2; tm++) {
        int r0 = row0 + mBase + tm * 16 + qrow;
        #pragma unroll
        for (int tn = 0; tn < 4; tn++) {
            int c = nBase + tn * 8 + qcol;
            float bx = b2[c], by = b2[c + 1];
            float2 o0 = make_float2(acc[tm][tn][0] + bx, acc[tm][tn][1] + by);
            float2 o1 = make_float2(acc[tm][tn][2] + bx, acc[tm][tn][3] + by);
            if (do_mish) {
                o0.x = mishf(o0.x); o0.y = mishf(o0.y);
                o1.x = mishf(o1.x); o1.y = mishf(o1.y);
            }
            if (r0 < NN)     *(float2*)(out + (size_t)r0 * DIN + c) = o0;
            if (r0 + 8 < NN) *(float2*)(out + (size_t)(r0 + 8) * DIN + c) = o1;
        }
    }
}

// ---------------- host launch ----------------
extern "C" void kernel_launch(void* const* d_in, const int* in_sizes, int n_in,
                              void* d_out, int out_size) {
    const float* x     = (const float*)d_in[0];
    const void*  ei    = (const void*)d_in[1];
    const float* W1    = (const float*)d_in[2];
    const float* b1    = (const float*)d_in[3];
    const float* gamma = (const float*)d_in[4];
    const float* beta  = (const float*)d_in[5];
    const float* W2    = (const float*)d_in[6];
    const float* b2    = (const float*)d_in[7];
    float*       out   = (float*)d_out;

    // ---- setup: 5 launches ----
    k_convert<<<CONV_BLOCKS, 256>>>(ei);               // convert + hist, 4 edges/thread
    k_scan_local<<<SCAN_BLOCKS, 1024>>>();             // warp-shuffle scan
    k_scan_add<<<(NN + 255) / 256, 256>>>();           // includes top-scan + deg re-zero
    k_scatter<<<CONV_BLOCKS, 256>>>();                 // 4 edges/thread
    k_prepw<<<64, 256>>>(W1, W2);

    const int AGG_BLOCKS  = (NN * 32 + 255) / 256;     // warp per node, 6250
    const int GEMM_BLOCKS = (NN + 127) / 128;          // 391

    for (int l = 0; l < 4; l++) {
        int src_sel = (l == 0) ? 0 : ((l & 1) ? 1 : 2);
        int dst_sel = (l == 3) ? 2 : (l & 1);

        k_agg<<<AGG_BLOCKS, 256>>>(x, src_sel);
        k_gemm1_mma<<<GEMM_BLOCKS, 256>>>(b1 + (size_t)l * DH, l);
        k_bnstat<<<GEMM_BLOCKS, 256>>>();
        k_gemm2_mma<<<GEMM_BLOCKS, 256>>>(b2 + (size_t)l * DIN,
                                          gamma + (size_t)l * DH, beta + (size_t)l * DH,
                                          out, l, dst_sel, (l < 3) ? 1 : 0);
    }
}

// round 17
// speedup vs baseline: 1.4554x; 1.4554x over previous
#include <cuda_runtime.h>
#include <cuda_bf16.h>
#include <math.h>
#include <stdint.h>

#define NN 50000
#define NE 800000
#define DIN 64
#define DH  128

// ---------------- device scratch (static, no allocation) ----------------
__device__ float g_bufA[NN * DIN];
__device__ float g_bufB[NN * DIN];
__device__ float g_agg[NN * DIN];
__device__ float g_h1[NN * DH];
__device__ int   g_src[NE];
__device__ int   g_dst[NE];
__device__ int   g_deg[NN];     // zero-initialized; re-zeroed by k_scan_add each call
__device__ int   g_off[NN + 1];
__device__ int   g_cur[NN];
__device__ int   g_csr[NE];
__device__ int   g_bsum[64];
__device__ float g_bn[2 * DH];
// baked weights in mma-fragment order: uint4 = {b0hi, b1hi, b0lo, b1lo}
__device__ uint4 g_w1f[4][4][16][32];
__device__ uint4 g_w2f[4][8][8][32];

// ================= mma helpers (sm_80+ PTX, compiles for compute_103) =================
__device__ __forceinline__ uint32_t smem_u32(const void* p) {
    uint32_t a;
    asm("{ .reg .u64 t; cvta.to.shared.u64 t, %1; cvt.u32.u64 %0, t; }" : "=r"(a) : "l"(p));
    return a;
}
__device__ __forceinline__ void ldmat4(uint32_t* r, uint32_t addr) {
    asm volatile("ldmatrix.sync.aligned.m8n8.x4.shared.b16 {%0,%1,%2,%3}, [%4];"
                 : "=r"(r[0]), "=r"(r[1]), "=r"(r[2]), "=r"(r[3]) : "r"(addr));
}
__device__ __forceinline__ void mma_bf16(float* d, const uint32_t* a, uint32_t b0, uint32_t b1) {
    asm volatile("mma.sync.aligned.m16n8k16.row.col.f32.bf16.bf16.f32 "
                 "{%0,%1,%2,%3}, {%4,%5,%6,%7}, {%8,%9}, {%0,%1,%2,%3};"
                 : "+f"(d[0]), "+f"(d[1]), "+f"(d[2]), "+f"(d[3])
                 : "r"(a[0]), "r"(a[1]), "r"(a[2]), "r"(a[3]), "r"(b0), "r"(b1));
}
__device__ __forceinline__ uint32_t pack_hi2(float x, float y, uint32_t& lo) {
    __nv_bfloat16 hx = __float2bfloat16(x), hy = __float2bfloat16(y);
    __nv_bfloat16 lx = __float2bfloat16(x - __bfloat162float(hx));
    __nv_bfloat16 ly = __float2bfloat16(y - __bfloat162float(hy));
    lo = ((uint32_t)__bfloat16_as_ushort(ly) << 16) | __bfloat16_as_ushort(lx);
    return ((uint32_t)__bfloat16_as_ushort(hy) << 16) | __bfloat16_as_ushort(hx);
}

// ---------------- convert + hist fused ----------------
__global__ __launch_bounds__(256) void k_convert(const void* __restrict__ ei) {
    __shared__ int s_is32;
    int tid = threadIdx.x;
    if (tid < 32) {
        const long long* p = (const long long*)ei;
        int bad = 0;
        #pragma unroll
        for (int u = 0; u < 8; u++) {
            long long v = p[tid * 8 + u];
            bad |= (v < 0 || v >= NN) ? 1 : 0;
        }
        unsigned m = __ballot_sync(0xffffffffu, bad);
        if (tid == 0) s_is32 = (m != 0u);
    }
    __syncthreads();
    int e = blockIdx.x * 256 + tid;
    if (e >= NE) return;
    int s, d;
    if (s_is32) {
        const int* p = (const int*)ei;
        s = p[e]; d = p[NE + e];
    } else {
        const long long* p = (const long long*)ei;
        s = (int)p[e]; d = (int)p[NE + e];
    }
    s = min(max(s, 0), NN - 1);
    d = min(max(d, 0), NN - 1);
    g_src[e] = s;
    g_dst[e] = d;
    atomicAdd(&g_deg[d], 1);
}

// ---------------- CSR build ----------------
#define SCAN_BLOCKS ((NN + 1023) / 1024)   // 49
__global__ void k_scan_local() {
    __shared__ int sh[1024];
    int tid = threadIdx.x;
    int gid = blockIdx.x * 1024 + tid;
    int v = (gid < NN) ? g_deg[gid] : 0;
    sh[tid] = v;
    __syncthreads();
    for (int o = 1; o < 1024; o <<= 1) {
        int t = (tid >= o) ? sh[tid - o] : 0;
        __syncthreads();
        sh[tid] += t;
        __syncthreads();
    }
    if (gid < NN) g_off[gid] = sh[tid] - v;   // exclusive partial
    if (tid == 1023) g_bsum[blockIdx.x] = sh[1023];
}
// scan_add: every block redundantly computes the 49-entry top-level inclusive
// prefix in smem (cheap), then applies it; also re-zeroes g_deg for next call.
__global__ __launch_bounds__(256) void k_scan_add() {
    __shared__ int sb[64];
    int tid = threadIdx.x;
    if (tid < 64) sb[tid] = (tid < SCAN_BLOCKS) ? g_bsum[tid] : 0;
    __syncthreads();
    for (int o = 1; o < 64; o <<= 1) {
        int t = (tid >= o && tid < 64) ? sb[tid - o] : 0;
        __syncthreads();
        if (tid < 64) sb[tid] += t;           // inclusive
        __syncthreads();
    }
    int i = blockIdx.x * 256 + tid;
    if (i < NN) {
        int blk = i >> 10;
        int add = blk ? sb[blk - 1] : 0;
        int o = g_off[i] + add;
        g_off[i] = o;
        g_cur[i] = o;
        g_deg[i] = 0;                         // ready for next call's convert+hist
    }
    if (i == 0) g_off[NN] = NE;
}
__global__ void k_scatter() {
    int e = blockIdx.x * blockDim.x + threadIdx.x;
    if (e < NE) {
        int d = g_dst[e];
        int p = atomicAdd(&g_cur[d], 1);
        g_csr[p] = g_src[e];
    }
}

// ---------------- weight bake: fp32 -> bf16 hi/lo fragment-order uint4 ----------------
__global__ void k_prepw(const float* __restrict__ W1, const float* __restrict__ W2) {
    int i = blockIdx.x * blockDim.x + threadIdx.x;
    if (i < 8192) {
        int lane = i & 31, n8 = (i >> 5) & 15, kstep = (i >> 9) & 3, l = i >> 11;
        int n = n8 * 8 + (lane >> 2);
        int k0 = kstep * 16 + 2 * (lane & 3);
        const float* W = W1 + (size_t)l * 8192;       // [k=64][n=128]
        float f00 = W[(k0 + 0) * 128 + n], f01 = W[(k0 + 1) * 128 + n];
        float f10 = W[(k0 + 8) * 128 + n], f11 = W[(k0 + 9) * 128 + n];
        uint4 w;
        w.x = pack_hi2(f00, f01, w.z);
        w.y = pack_hi2(f10, f11, w.w);
        g_w1f[l][kstep][n8][lane] = w;
    } else if (i < 16384) {
        int j = i - 8192;
        int lane = j & 31, n8 = (j >> 5) & 7, kstep = (j >> 8) & 7, l = j >> 11;
        int n = n8 * 8 + (lane >> 2);
        int k0 = kstep * 16 + 2 * (lane & 3);
        const float* W = W2 + (size_t)l * 8192;       // [k=128][n=64]
        float f00 = W[(k0 + 0) * 64 + n], f01 = W[(k0 + 1) * 64 + n];
        float f10 = W[(k0 + 8) * 64 + n], f11 = W[(k0 + 9) * 64 + n];
        uint4 w;
        w.x = pack_hi2(f00, f01, w.z);
        w.y = pack_hi2(f10, f11, w.w);
        g_w2f[l][kstep][n8][lane] = w;
    }
}

// ---------------- softmax aggregation: warp per node, manual 4-wide unroll ----------------
// shift-free + eps-hoisted (R9 derivation). Manual unroll issues 4 csr loads and
// 4 independent row gathers per iteration (MLP=4) to break the csr->gather
// latency chain that bound the previous version. Uniform trip count per warp.
// Block 0 zeroes g_bn for this layer's bnstat accumulation.
__global__ __launch_bounds__(256) void k_agg(const float* __restrict__ xin, int src_sel) {
    if (blockIdx.x == 0 && threadIdx.x < 2 * DH) g_bn[threadIdx.x] = 0.f;
    const float* x = (src_sel == 0) ? xin : (src_sel == 1) ? g_bufA : g_bufB;
    int w = (blockIdx.x * blockDim.x + threadIdx.x) >> 5;
    if (w >= NN) return;
    int lane = threadIdx.x & 31;
    int beg = g_off[w], end = g_off[w + 1];
    int c = lane * 2;

    float d0 = 0.f, d1 = 0.f, n0 = 0.f, n1 = 0.f;
    int j = beg;
    #pragma unroll 1
    for (; j + 4 <= end; j += 4) {
        int s0 = g_csr[j], s1 = g_csr[j + 1], s2 = g_csr[j + 2], s3 = g_csr[j + 3];
        float2 va = *(const float2*)(x + (size_t)s0 * DIN + c);
        float2 vb = *(const float2*)(x + (size_t)s1 * DIN + c);
        float2 vc = *(const float2*)(x + (size_t)s2 * DIN + c);
        float2 vd = *(const float2*)(x + (size_t)s3 * DIN + c);
        float ma0 = fmaxf(va.x, 0.f), ma1 = fmaxf(va.y, 0.f);
        float mb0 = fmaxf(vb.x, 0.f), mb1 = fmaxf(vb.y, 0.f);
        float mc0 = fmaxf(vc.x, 0.f), mc1 = fmaxf(vc.y, 0.f);
        float md0 = fmaxf(vd.x, 0.f), md1 = fmaxf(vd.y, 0.f);
        float ea0 = __expf(ma0), ea1 = __expf(ma1);
        float eb0 = __expf(mb0), eb1 = __expf(mb1);
        float ec0 = __expf(mc0), ec1 = __expf(mc1);
        float ed0 = __expf(md0), ed1 = __expf(md1);
        d0 += ea0; n0 = fmaf(ma0, ea0, n0);
        d1 += ea1; n1 = fmaf(ma1, ea1, n1);
        d0 += eb0; n0 = fmaf(mb0, eb0, n0);
        d1 += eb1; n1 = fmaf(mb1, eb1, n1);
        d0 += ec0; n0 = fmaf(mc0, ec0, n0);
        d1 += ec1; n1 = fmaf(mc1, ec1, n1);
        d0 += ed0; n0 = fmaf(md0, ed0, n0);
        d1 += ed1; n1 = fmaf(md1, ed1, n1);
    }
    #pragma unroll 1
    for (; j < end; j++) {
        int s = g_csr[j];
        float2 v = *(const float2*)(x + (size_t)s * DIN + c);
        float m0 = fmaxf(v.x, 0.f);
        float m1 = fmaxf(v.y, 0.f);
        float e0 = __expf(m0);
        float e1 = __expf(m1);
        d0 += e0;  n0 = fmaf(m0, e0, n0);
        d1 += e1;  n1 = fmaf(m1, e1, n1);
    }
    float epsb = (beg < end) ? 1e-7f : 0.f;
    float2 xc = *(const float2*)(x + (size_t)w * DIN + c);
    float2 o;
    o.x = n0 / (d0 + 1e-16f) + epsb + xc.x;
    o.y = n1 / (d1 + 1e-16f) + epsb + xc.y;
    *(float2*)(g_agg + (size_t)w * DIN + c) = o;
}

// ---------------- BN stats (separate, cheap L2-read kernel — do NOT fuse into GEMM1) ----------------
__global__ __launch_bounds__(256) void k_bnstat() {
    __shared__ float ss[256], sq[256];
    int col = threadIdx.x & 127;
    int half = threadIdx.x >> 7;
    float s = 0.f, q = 0.f;
    for (int r = blockIdx.x * 2 + half; r < NN; r += gridDim.x * 2) {
        float v = g_h1[(size_t)r * DH + col];
        s += v; q += v * v;
    }
    ss[threadIdx.x] = s; sq[threadIdx.x] = q;
    __syncthreads();
    if (half == 0) {
        atomicAdd(&g_bn[col], ss[col] + ss[col + 128]);
        atomicAdd(&g_bn[DH + col], sq[col] + sq[col + 128]);
    }
}

// ---------------- GEMM1 (mma.sync bf16 split): h1 = agg @ W1 + b1  [128/blk x 128 x K64] ----------------
#define LDA1 72
__global__ __launch_bounds__(256) void k_gemm1_mma(const float* __restrict__ b1, int layer) {
    __shared__ __nv_bfloat16 Ahi[128 * LDA1];
    __shared__ __nv_bfloat16 Alo[128 * LDA1];
    int tid = threadIdx.x, lane = tid & 31, wid = tid >> 5;
    int row0 = blockIdx.x * 128;

    // convert A tile: 128 x 64 fp32 -> hi/lo bf16
    #pragma unroll
    for (int it = 0; it < 16; it++) {
        int f = tid + it * 256;
        int r = f >> 5, c2 = f & 31;
        int row = row0 + r;
        float2 v = make_float2(0.f, 0.f);
        if (row < NN) v = *(const float2*)(g_agg + (size_t)row * DIN + c2 * 2);
        uint32_t lp, hp = pack_hi2(v.x, v.y, lp);
        *(uint32_t*)&Ahi[r * LDA1 + c2 * 2] = hp;
        *(uint32_t*)&Alo[r * LDA1 + c2 * 2] = lp;
    }
    __syncthreads();

    int wm = wid & 3, wn = wid >> 2;      // warp tile: 32 rows x 64 cols
    int mBase = wm * 32, nBase = wn * 64;
    uint32_t a_hi = smem_u32(Ahi), a_lo = smem_u32(Alo);

    float acc[2][8][4];
    #pragma unroll
    for (int tm = 0; tm < 2; tm++)
        #pragma unroll
        for (int tn = 0; tn < 8; tn++)
            #pragma unroll
            for (int q = 0; q < 4; q++) acc[tm][tn][q] = 0.f;

    int lrow = lane & 15;
    int lkof = (lane >> 4) << 3;
    #pragma unroll
    for (int ks = 0; ks < 4; ks++) {
        uint32_t ah[2][4], al[2][4];
        #pragma unroll
        for (int tm = 0; tm < 2; tm++) {
            uint32_t off = ((mBase + tm * 16 + lrow) * LDA1 + ks * 16 + lkof) * 2;
            ldmat4(ah[tm], a_hi + off);
            ldmat4(al[tm], a_lo + off);
        }
        uint4 w[8];
        #pragma unroll
        for (int tn = 0; tn < 8; tn++)
            w[tn] = g_w1f[layer][ks][wn * 8 + tn][lane];
        #pragma unroll
        for (int tm = 0; tm < 2; tm++)
            #pragma unroll
            for (int tn = 0; tn < 8; tn++) {
                mma_bf16(acc[tm][tn], ah[tm], w[tn].x, w[tn].y);
                mma_bf16(acc[tm][tn], ah[tm], w[tn].z, w[tn].w);
                mma_bf16(acc[tm][tn], al[tm], w[tn].x, w[tn].y);
            }
    }

    // epilogue: + bias, store h1 (nothing else — epilogue is register-saturated)
    int qrow = lane >> 2, qcol = (lane & 3) * 2;
    #pragma unroll
    for (int tm = 0; tm < 2; tm++) {
        int r0 = row0 + mBase + tm * 16 + qrow;
        #pragma unroll
        for (int tn = 0; tn < 8; tn++) {
            int c = nBase + tn * 8 + qcol;
            float bx = b1[c], by = b1[c + 1];
            if (r0 < NN)
                *(float2*)(g_h1 + (size_t)r0 * DH + c) = make_float2(acc[tm][tn][0] + bx, acc[tm][tn][1] + by);
            if (r0 + 8 < NN)
                *(float2*)(g_h1 + (size_t)(r0 + 8) * DH + c) = make_float2(acc[tm][tn][2] + bx, acc[tm][tn][3] + by);
        }
    }
}

// ---------------- mish ----------------
__device__ __forceinline__ float mishf(float v) {
    float e  = __expf(v);
    float sp = (v > 15.f) ? v : log1pf(e);
    return v * tanhf(sp);
}

// ---------------- GEMM2 (mma.sync bf16 split) + inline BN finalize ----------------
#define LDA2 136
__global__ __launch_bounds__(256) void k_gemm2_mma(const float* __restrict__ b2,
                                                   const float* __restrict__ gamma,
                                                   const float* __restrict__ beta,
                                                   float* __restrict__ outp,
                                                   int layer, int dst_sel, int do_mish) {
    __shared__ __nv_bfloat16 Ahi[128 * LDA2];
    __shared__ __nv_bfloat16 Alo[128 * LDA2];
    __shared__ float ssc[DH], ssh[DH];
    int tid = threadIdx.x, lane = tid & 31, wid = tid >> 5;
    float* out = (dst_sel == 0) ? g_bufA : (dst_sel == 1) ? g_bufB : outp;

    if (tid < DH) {
        float mu  = g_bn[tid] * (1.0f / NN);
        float var = g_bn[DH + tid] * (1.0f / NN) - mu * mu;
        float rs  = rsqrtf(var + 1e-5f);
        float sc  = rs * gamma[tid];
        ssc[tid] = sc;
        ssh[tid] = beta[tid] - mu * sc;
    }
    __syncthreads();

    int row0 = blockIdx.x * 128;
    #pragma unroll
    for (int it = 0; it < 32; it++) {
        int f = tid + it * 256;
        int r = f >> 6, c2 = f & 63;
        int row = row0 + r;
        float2 v = make_float2(0.f, 0.f);
        if (row < NN) v = *(const float2*)(g_h1 + (size_t)row * DH + c2 * 2);
        int c = c2 * 2;
        float a0 = fmaxf(fmaf(v.x, ssc[c], ssh[c]), 0.f);
        float a1 = fmaxf(fmaf(v.y, ssc[c + 1], ssh[c + 1]), 0.f);
        uint32_t lp, hp = pack_hi2(a0, a1, lp);
        *(uint32_t*)&Ahi[r * LDA2 + c] = hp;
        *(uint32_t*)&Alo[r * LDA2 + c] = lp;
    }
    __syncthreads();

    int wm = wid & 3, wn = wid >> 2;      // warp tile: 32 rows x 32 cols
    int mBase = wm * 32, nBase = wn * 32;
    uint32_t a_hi = smem_u32(Ahi), a_lo = smem_u32(Alo);

    float acc[2][4][4];
    #pragma unroll
    for (int tm = 0; tm < 2; tm++)
        #pragma unroll
        for (int tn = 0; tn < 4; tn++)
            #pragma unroll
            for (int q = 0; q < 4; q++) acc[tm][tn][q] = 0.f;

    int lrow = lane & 15;
    int lkof = (lane >> 4) << 3;
    #pragma unroll
    for (int ks = 0; ks < 8; ks++) {
        uint32_t ah[2][4], al[2][4];
        #pragma unroll
        for (int tm = 0; tm < 2; tm++) {
            uint32_t off = ((mBase + tm * 16 + lrow) * LDA2 + ks * 16 + lkof) * 2;
            ldmat4(ah[tm], a_hi + off);
            ldmat4(al[tm], a_lo + off);
        }
        uint4 w[4];
        #pragma unroll
        for (int tn = 0; tn < 4; tn++)
            w[tn] = g_w2f[layer][ks][wn * 4 + tn][lane];
        #pragma unroll
        for (int tm = 0; tm < 2; tm++)
            #pragma unroll
            for (int tn = 0; tn < 4; tn++) {
                mma_bf16(acc[tm][tn], ah[tm], w[tn].x, w[tn].y);
                mma_bf16(acc[tm][tn], ah[tm], w[tn].z, w[tn].w);
                mma_bf16(acc[tm][tn], al[tm], w[tn].x, w[tn].y);
            }
    }

    int qrow = lane >> 2, qcol = (lane & 3) * 2;
    #pragma unroll
    for (int tm = 0; tm < 2; tm++) {
        int r0 = row0 + mBase + tm * 16 + qrow;
        #pragma unroll
        for (int tn = 0; tn < 4; tn++) {
            int c = nBase + tn * 8 + qcol;
            float bx = b2[c], by = b2[c + 1];
            float2 o0 = make_float2(acc[tm][tn][0] + bx, acc[tm][tn][1] + by);
            float2 o1 = make_float2(acc[tm][tn][2] + bx, acc[tm][tn][3] + by);
            if (do_mish) {
                o0.x = mishf(o0.x); o0.y = mishf(o0.y);
                o1.x = mishf(o1.x); o1.y = mishf(o1.y);
            }
            if (r0 < NN)     *(float2*)(out + (size_t)r0 * DIN + c) = o0;
            if (r0 + 8 < NN) *(float2*)(out + (size_t)(r0 + 8) * DIN + c) = o1;
        }
    }
}

// ---------------- host launch ----------------
extern "C" void kernel_launch(void* const* d_in, const int* in_sizes, int n_in,
                              void* d_out, int out_size) {
    const float* x     = (const float*)d_in[0];
    const void*  ei    = (const void*)d_in[1];
    const float* W1    = (const float*)d_in[2];
    const float* b1    = (const float*)d_in[3];
    const float* gamma = (const float*)d_in[4];
    const float* beta  = (const float*)d_in[5];
    const float* W2    = (const float*)d_in[6];
    const float* b2    = (const float*)d_in[7];
    float*       out   = (float*)d_out;

    // ---- setup: 5 launches ----
    k_convert<<<(NE + 255) / 256, 256>>>(ei);          // convert + hist (deg pre-zeroed)
    k_scan_local<<<SCAN_BLOCKS, 1024>>>();
    k_scan_add<<<(NN + 255) / 256, 256>>>();           // includes top-scan + deg re-zero
    k_scatter<<<(NE + 255) / 256, 256>>>();
    k_prepw<<<64, 256>>>(W1, W2);

    const int AGG_BLOCKS  = (NN * 32 + 255) / 256;     // warp per node, 6250
    const int GEMM_BLOCKS = (NN + 127) / 128;          // 391

    for (int l = 0; l < 4; l++) {
        int src_sel = (l == 0) ? 0 : ((l & 1) ? 1 : 2);
        int dst_sel = (l == 3) ? 2 : (l & 1);

        k_agg<<<AGG_BLOCKS, 256>>>(x, src_sel);
        k_gemm1_mma<<<GEMM_BLOCKS, 256>>>(b1 + (size_t)l * DH, l);
        k_bnstat<<<GEMM_BLOCKS, 256>>>();
        k_gemm2_mma<<<GEMM_BLOCKS, 256>>>(b2 + (size_t)l * DIN,
                                          gamma + (size_t)l * DH, beta + (size_t)l * DH,
                                          out, l, dst_sel, (l < 3) ? 1 : 0);
    }
}